// round 8
// baseline (speedup 1.0000x reference)
#include <cuda_runtime.h>
#include <cuda_bf16.h>
#include <cstdint>
#include <cfloat>

// ---------------------------------------------------------------------------
// AttentionBasedRewiring — R1-proven FFMA2 architecture, re-tuned:
//   * 512 threads / CTA (16 warps: 4 per SMSP, vs R1's 2) for latency hiding
//   * 4x8 microtile per thread, same 128x128 tile, same cp.async k loader
//   * scan split 4-ways per row + exact 4-way merge (ties -> lower index)
// Plus a 1-warp mma.sync canary (writes only to private scratch) to bisect
// the R3-R6 illegal-access mystery without risking the main path's logic.
// ---------------------------------------------------------------------------

#define N_NODES 65536
#define D_IN    512
#define HDIM    128
#define TOPK    8
#define BM      128
#define BN      128
#define NT      (N_NODES / BN)      // 512
#define PITCH   136                 // qs/ks pitch (floats)
#define SPITCH  132                 // sims pitch (floats) — 4-way max conflicts
#define TPB     512

#define QS_OFF  0
#define KS_OFF  (HDIM * PITCH * 4)                 // 69632
#define SIM_OFF (2 * HDIM * PITCH * 4)             // 139264
#define SMEM_TOTAL (SIM_OFF + BM * SPITCH * 4)     // 206848

__device__ float g_q [(size_t)N_NODES * HDIM];     // [node][h]
__device__ float g_kT[(size_t)HDIM * N_NODES];     // [h][node]
__device__ float g_canary[128];                    // mma canary scratch

// ---------------- packed f32x2 helpers (proven in R1) ----------------------
__device__ __forceinline__ void fma2(unsigned long long& d,
                                     unsigned long long a,
                                     unsigned long long b) {
    asm("fma.rn.f32x2 %0, %1, %2, %0;" : "+l"(d) : "l"(a), "l"(b));
}
__device__ __forceinline__ unsigned long long splat2(float a) {
    unsigned long long r;
    asm("mov.b64 %0, {%1, %1};" : "=l"(r) : "f"(a));
    return r;
}

__device__ __forceinline__ void mma_bf16(float* c, const uint32_t a[4],
                                         uint32_t b0, uint32_t b1) {
    asm volatile(
        "mma.sync.aligned.m16n8k16.row.col.f32.bf16.bf16.f32 "
        "{%0,%1,%2,%3}, {%4,%5,%6,%7}, {%8,%9}, {%0,%1,%2,%3};"
        : "+f"(c[0]), "+f"(c[1]), "+f"(c[2]), "+f"(c[3])
        : "r"(a[0]), "r"(a[1]), "r"(a[2]), "r"(a[3]), "r"(b0), "r"(b1));
}

// ---------------------------------------------------------------------------
// mma.sync canary: 1 warp, smem-built fragments, writes ONLY g_canary.
// ---------------------------------------------------------------------------
__device__ __forceinline__ uint32_t packbf(float lo, float hi) {
    return (__float_as_uint(hi) & 0xFFFF0000u) | (__float_as_uint(lo) >> 16);
}

__global__ void mma_canary_kernel() {
    __shared__ __align__(16) uint32_t As[128];   // 16x16 bf16, row r: As[r*8+k2]
    __shared__ __align__(16) uint32_t Bs[128];   // 16(n) x 16(k)
    const int lane = threadIdx.x & 31;
    for (int i = lane; i < 128; i += 32) {
        As[i] = packbf(0.125f * (float)(i % 13) - 0.7f, 0.25f * (float)(i % 7) - 0.8f);
        Bs[i] = packbf(0.1f * (float)(i % 11) - 0.5f, 0.2f * (float)(i % 5) - 0.4f);
    }
    __syncwarp();
    const int g = lane >> 2, t = lane & 3;
    uint32_t A[4] = {As[g * 8 + t], As[(g + 8) * 8 + t],
                     As[g * 8 + t + 4], As[(g + 8) * 8 + t + 4]};
    float c[4] = {0.f, 0.f, 0.f, 0.f};
    mma_bf16(c, A, Bs[g * 8 + t], Bs[g * 8 + t + 4]);
    g_canary[lane * 4 + 0] = c[0];
    g_canary[lane * 4 + 1] = c[1];
    g_canary[lane * 4 + 2] = c[2];
    g_canary[lane * 4 + 3] = c[3];
}

// ---------------------------------------------------------------------------
// Kernel 1: Q = x@Wq + bq (natural), kT = (x@Wk + bk)^T  (verbatim from R1)
// ---------------------------------------------------------------------------
__global__ __launch_bounds__(256) void qk_kernel(const float* __restrict__ x,
                                                 const float* __restrict__ Wq,
                                                 const float* __restrict__ bq,
                                                 const float* __restrict__ Wk,
                                                 const float* __restrict__ bk) {
    const int zz = blockIdx.y;
    const float* __restrict__ W    = zz ? Wk : Wq;
    const float* __restrict__ bias = zz ? bk : bq;
    const int r0 = blockIdx.x * 128;

    __shared__ float xs[32][PITCH];
    __shared__ float ws[32][PITCH];

    const int tid = threadIdx.x;
    const int tx = tid & 15;
    const int ty = tid >> 4;

    float acc[8][8];
#pragma unroll
    for (int i = 0; i < 8; ++i)
#pragma unroll
        for (int j = 0; j < 8; ++j) acc[i][j] = 0.f;

    for (int kc = 0; kc < D_IN; kc += 32) {
        {
            const int r = tid >> 1, kq = tid & 1;
#pragma unroll
            for (int j = 0; j < 4; ++j) {
                float4 v = *(const float4*)&x[(size_t)(r0 + r) * D_IN + kc + kq * 16 + j * 4];
                const int kk = kq * 16 + j * 4;
                xs[kk + 0][r] = v.x; xs[kk + 1][r] = v.y;
                xs[kk + 2][r] = v.z; xs[kk + 3][r] = v.w;
            }
            const int kr = tid >> 3, cq = tid & 7;
#pragma unroll
            for (int j = 0; j < 4; ++j) {
                *(float4*)&ws[kr][cq * 16 + j * 4] =
                    *(const float4*)&W[(size_t)(kc + kr) * HDIM + cq * 16 + j * 4];
            }
        }
        __syncthreads();

#pragma unroll 8
        for (int k = 0; k < 32; ++k) {
            float4 a0 = *(const float4*)&xs[k][4 * ty];
            float4 a1 = *(const float4*)&xs[k][64 + 4 * ty];
            float4 b0 = *(const float4*)&ws[k][4 * tx];
            float4 b1 = *(const float4*)&ws[k][64 + 4 * tx];
            float av[8] = {a0.x, a0.y, a0.z, a0.w, a1.x, a1.y, a1.z, a1.w};
            float bv[8] = {b0.x, b0.y, b0.z, b0.w, b1.x, b1.y, b1.z, b1.w};
#pragma unroll
            for (int i = 0; i < 8; ++i)
#pragma unroll
                for (int j = 0; j < 8; ++j) acc[i][j] += av[i] * bv[j];
        }
        __syncthreads();
    }

    if (zz == 0) {
#pragma unroll
        for (int i = 0; i < 8; ++i) {
            const int rm = (i < 4) ? (4 * ty + i) : (64 + 4 * ty + i - 4);
            float4 o0, o1;
            o0.x = acc[i][0] + bias[4 * tx + 0];
            o0.y = acc[i][1] + bias[4 * tx + 1];
            o0.z = acc[i][2] + bias[4 * tx + 2];
            o0.w = acc[i][3] + bias[4 * tx + 3];
            o1.x = acc[i][4] + bias[64 + 4 * tx + 0];
            o1.y = acc[i][5] + bias[64 + 4 * tx + 1];
            o1.z = acc[i][6] + bias[64 + 4 * tx + 2];
            o1.w = acc[i][7] + bias[64 + 4 * tx + 3];
            *(float4*)&g_q[(size_t)(r0 + rm) * HDIM + 4 * tx]      = o0;
            *(float4*)&g_q[(size_t)(r0 + rm) * HDIM + 64 + 4 * tx] = o1;
        }
    } else {
#pragma unroll
        for (int j = 0; j < 8; ++j) {
            const int cm = (j < 4) ? (4 * tx + j) : (64 + 4 * tx + j - 4);
            const float bb = bias[cm];
            float4 o0, o1;
            o0.x = acc[0][j] + bb; o0.y = acc[1][j] + bb;
            o0.z = acc[2][j] + bb; o0.w = acc[3][j] + bb;
            o1.x = acc[4][j] + bb; o1.y = acc[5][j] + bb;
            o1.z = acc[6][j] + bb; o1.w = acc[7][j] + bb;
            *(float4*)&g_kT[(size_t)cm * N_NODES + r0 + 4 * ty]      = o0;
            *(float4*)&g_kT[(size_t)cm * N_NODES + r0 + 64 + 4 * ty] = o1;
        }
    }
}

// ---------------------------------------------------------------------------
// Kernel 2: fused sim GEMM + top-8, 512 threads, 4x8 microtile
// ---------------------------------------------------------------------------
__device__ __forceinline__ void topk_ins(float v, int c, float tv[TOPK], int ti[TOPK]) {
    if (v <= tv[7]) return;
    int pos = 8;
#pragma unroll
    for (int p = 7; p >= 0; --p)
        if (tv[p] < v) pos = p;
#pragma unroll
    for (int p = 7; p > 0; --p)
        if (p > pos) { tv[p] = tv[p - 1]; ti[p] = ti[p - 1]; }
#pragma unroll
    for (int p = 0; p < 8; ++p)
        if (p == pos) { tv[p] = v; ti[p] = c; }
}

__global__ __launch_bounds__(TPB, 1) void sim_topk_kernel(float* __restrict__ out) {
    extern __shared__ float sm[];
    float* qs   = sm;                           // [HDIM][PITCH]  ([h][row])
    float* ks   = sm + HDIM * PITCH;            // [HDIM][PITCH]  ([h][col])
    float* sims = sm + 2 * HDIM * PITCH;        // [BM][SPITCH]

    const int tid = threadIdx.x;
    const int tx = tid & 15;                    // col group
    const int ty = tid >> 4;                    // row group 0..31
    const int srow = tid & 127;                 // scan: owned row
    const int sq   = tid >> 7;                  // scan: col quarter 0..3
    const int r0 = blockIdx.x * BM;

    const int lh = tid >> 2;                    // loader: h row 0..127
    const int lq = tid & 3;                     // loader: col quarter

    // ---- prologue: q tile -> qs transposed; async-load ks tile 0 ----
    {
        const float* qsrc = g_q + (size_t)(r0 + lh) * HDIM + 32 * lq;
#pragma unroll
        for (int j = 0; j < 8; ++j) {
            float4 v = *(const float4*)(qsrc + 4 * j);
            const int h = 32 * lq + 4 * j;
            qs[(h + 0) * PITCH + lh] = v.x;
            qs[(h + 1) * PITCH + lh] = v.y;
            qs[(h + 2) * PITCH + lh] = v.z;
            qs[(h + 3) * PITCH + lh] = v.w;
        }
    }

#define KS_LOAD(t)                                                              \
    do {                                                                        \
        const float* gsrc_ = g_kT + (size_t)lh * N_NODES + (size_t)(t) * BN + 32 * lq; \
        uint32_t sb_;                                                           \
        asm("{ .reg .u64 u; cvta.to.shared.u64 u, %1; cvt.u32.u64 %0, u; }"     \
            : "=r"(sb_) : "l"(ks + lh * PITCH + 32 * lq));                      \
        _Pragma("unroll")                                                       \
        for (int j = 0; j < 8; ++j)                                             \
            asm volatile("cp.async.cg.shared.global [%0], [%1], 16;"            \
                         :: "r"(sb_ + 16 * j), "l"(gsrc_ + 4 * j));             \
        asm volatile("cp.async.commit_group;");                                 \
    } while (0)

    KS_LOAD(0);

    float tv[TOPK];
    int   ti[TOPK];
#pragma unroll
    for (int j = 0; j < TOPK; ++j) { tv[j] = -FLT_MAX; ti[j] = 0; }

    for (int t = 0; t < NT; ++t) {
        asm volatile("cp.async.wait_group 0;" ::: "memory");
        __syncthreads();                        // ks tile t + (t==0: qs) ready

        // ---- GEMM: 4x8 microtile, packed f32x2 ----
        unsigned long long acc[4][4];
#pragma unroll
        for (int i = 0; i < 4; ++i)
#pragma unroll
            for (int p = 0; p < 4; ++p) acc[i][p] = 0ull;

#pragma unroll 4
        for (int h = 0; h < HDIM; ++h) {
            float4 a = *(const float4*)&qs[h * PITCH + 4 * ty];
            ulonglong2 b0 = *(const ulonglong2*)&ks[h * PITCH + 4 * tx];
            ulonglong2 b1 = *(const ulonglong2*)&ks[h * PITCH + 64 + 4 * tx];
            unsigned long long s0 = splat2(a.x), s1 = splat2(a.y),
                               s2 = splat2(a.z), s3 = splat2(a.w);
            fma2(acc[0][0], s0, b0.x); fma2(acc[0][1], s0, b0.y);
            fma2(acc[0][2], s0, b1.x); fma2(acc[0][3], s0, b1.y);
            fma2(acc[1][0], s1, b0.x); fma2(acc[1][1], s1, b0.y);
            fma2(acc[1][2], s1, b1.x); fma2(acc[1][3], s1, b1.y);
            fma2(acc[2][0], s2, b0.x); fma2(acc[2][1], s2, b0.y);
            fma2(acc[2][2], s2, b1.x); fma2(acc[2][3], s2, b1.y);
            fma2(acc[3][0], s3, b0.x); fma2(acc[3][1], s3, b0.y);
            fma2(acc[3][2], s3, b1.x); fma2(acc[3][3], s3, b1.y);
        }
        __syncthreads();                        // done reading ks

        if (t + 1 < NT) KS_LOAD(t + 1);         // overlaps dump + scan

        // ---- dump sim tile ----
#pragma unroll
        for (int i = 0; i < 4; ++i) {
            const int row = 4 * ty + i;
            *(ulonglong2*)&sims[row * SPITCH + 4 * tx] =
                make_ulonglong2(acc[i][0], acc[i][1]);
            *(ulonglong2*)&sims[row * SPITCH + 64 + 4 * tx] =
                make_ulonglong2(acc[i][2], acc[i][3]);
        }
        __syncthreads();                        // sim tile visible

        // ---- scan: per (row, quarter) running top-8 ----
        const int cbase = t * BN + 32 * sq;
        const float* srp = &sims[srow * SPITCH + 32 * sq];
#pragma unroll
        for (int j4 = 0; j4 < 8; ++j4) {
            float4 v = *(const float4*)(srp + 4 * j4);
            float m = fmaxf(fmaxf(v.x, v.y), fmaxf(v.z, v.w));
            if (m > tv[7]) {
                const int c = cbase + 4 * j4;
                topk_ins(v.x, c + 0, tv, ti);
                topk_ins(v.y, c + 1, tv, ti);
                topk_ins(v.z, c + 2, tv, ti);
                topk_ins(v.w, c + 3, tv, ti);
            }
        }
    }
#undef KS_LOAD

    // ---- final 4-way merge per row (ties -> lower index) ----
    __syncthreads();
    float* mv = qs;                             // reuse qs region (16 KB)
    int*   mi = (int*)(qs + BM * 32);           // +16 KB
    {
        const int base = (srow * 4 + sq) * TOPK;
#pragma unroll
        for (int j = 0; j < TOPK; ++j) { mv[base + j] = tv[j]; mi[base + j] = ti[j]; }
    }
    __syncthreads();

    if (tid < 128) {
        int p[4] = {0, 0, 0, 0};
        const size_t g = (size_t)r0 + tid;
#pragma unroll
        for (int j = 0; j < TOPK; ++j) {
            float best = -FLT_MAX;
            int bidx = 0x7fffffff, bq = 0;
#pragma unroll
            for (int qd = 0; qd < 4; ++qd) {
                if (p[qd] < TOPK) {
                    const int o = (tid * 4 + qd) * TOPK + p[qd];
                    const float v = mv[o];
                    const int ix = mi[o];
                    if (v > best || (v == best && ix < bidx)) {
                        best = v; bidx = ix; bq = qd;
                    }
                }
            }
            out[g * TOPK + j] = best;
            out[(size_t)N_NODES * TOPK + g * TOPK + j] = (float)bidx;
            ++p[bq];
        }
    }
}

// ---------------------------------------------------------------------------
extern "C" void kernel_launch(void* const* d_in, const int* in_sizes, int n_in,
                              void* d_out, int out_size) {
    const float* x  = (const float*)d_in[0];
    const float* Wq = (const float*)d_in[1];
    const float* bq = (const float*)d_in[2];
    const float* Wk = (const float*)d_in[3];
    const float* bk = (const float*)d_in[4];
    float* out = (float*)d_out;

    mma_canary_kernel<<<1, 32>>>();             // bisect probe: mma.sync only

    qk_kernel<<<dim3(N_NODES / 128, 2), 256>>>(x, Wq, bq, Wk, bk);

    cudaFuncSetAttribute(sim_topk_kernel,
                         cudaFuncAttributeMaxDynamicSharedMemorySize, SMEM_TOTAL);
    sim_topk_kernel<<<N_NODES / BM, TPB, SMEM_TOTAL>>>(out);
}